// round 15
// baseline (speedup 1.0000x reference)
#include <cuda_runtime.h>
#include <cuda_fp16.h>
#include <math.h>
#include <cstdint>

#define D      256
#define R      16
#define N0     8192
#define L      6
#define NL     8192
#define TOTAL  (N0 + L * NL)   // 57344

#define K1 512
#define K2 256
#define NS1  4                 // K1/128 superstages
#define NS2  2                 // K2/128
#define NSTG (NS1 + NS2)       // 6

#define NSLOTS (L * 128 + 128) // 896 partial slots

// smem layout (halfs)
#define AS     544             // A row stride (K1+32): conflict-free LDS.128 phases
#define HS     288             // H row stride (aliases A region)
#define OFF_B  (64 * AS)                  // 34816 halfs
#define SLOT   32768                      // 64KB superstage: [h(2)][sub(4)][128n][32k]
#define SMEM_HALFS (OFF_B + 2 * SLOT)     // 100352
#define SMEM_BYTES (SMEM_HALFS * 2)       // 200704

// ---------------- scratch (device globals; no allocation) ----------------
__device__ __half g_storeh[(size_t)TOTAL * D];    // fp16 k-interleaved embeddings
__device__ __half g_W1h[(size_t)R * D * K1];      // [r][h(2)][s32(16)][128n][32k]
__device__ __half g_W2h[(size_t)R * D * K2];      // [r][h(2)][s32(8)][128n][32k]
__device__ float  g_partials[NSLOTS * 5];         // fully rewritten each run
__device__ int    g_donecnt;                      // layer-5 CTAs; reset by last CTA

__device__ __forceinline__ uint32_t smem_to_u32(const void* p) {
    uint32_t a;
    asm("{ .reg .u64 t; cvta.to.shared.u64 t, %1; cvt.u32.u64 %0, t; }" : "=r"(a) : "l"(p));
    return a;
}

__device__ __forceinline__ int pos32(int k5) {
    return ((k5 >> 1) & 3) * 8 + (k5 >> 4) * 4 + ((k5 >> 3) & 1) * 2 + (k5 & 1);
}

#define MBARRIER_INIT(mbar, cnt) \
    asm volatile("mbarrier.init.shared.b64 [%0], %1;" \
                 :: "r"((uint32_t)(mbar)), "r"((uint32_t)(cnt)) : "memory")
#define MBARRIER_EXPECT_TX(mbar, bytes) \
    asm volatile("mbarrier.arrive.expect_tx.shared.b64 _, [%0], %1;" \
                 :: "r"((uint32_t)(mbar)), "r"((uint32_t)(bytes)) : "memory")
#define MBARRIER_WAIT_PARITY(mbar_a, par) do { \
    uint32_t _m = (uint32_t)(mbar_a), _p = (uint32_t)(par), _d; \
    asm volatile("{\n\t.reg .pred p;\n\t" \
        "mbarrier.try_wait.parity.acquire.cta.shared::cta.b64 p, [%1], %2;\n\t" \
        "selp.b32 %0, 1, 0, p;\n\t}" : "=r"(_d) : "r"(_m), "r"(_p) : "memory"); \
    if (!_d) { \
        asm volatile("{\n\t.reg .pred P1;\n\t" \
            "WL_%=:\n\t" \
            "mbarrier.try_wait.parity.acquire.cta.shared::cta.b64 P1, [%0], %1, 0x989680;\n\t" \
            "@P1 bra.uni WD_%=;\n\t" \
            "bra.uni WL_%=;\n\t" \
            "WD_%=:\n\t}" :: "r"(_m), "r"(_p) : "memory"); \
    } \
} while (0)
#define BULK_G2S(dst_u32, src_ptr, bytes, mbar_u32) \
    asm volatile("cp.async.bulk.shared::cta.global.mbarrier::complete_tx::bytes " \
                 "[%0], [%1], %2, [%3];" \
                 :: "r"(dst_u32), "l"(src_ptr), "r"((uint32_t)(bytes)), \
                    "r"(mbar_u32) : "memory")

__device__ __forceinline__ float softplusf(float x) {
    return fmaxf(x, 0.f) + log1pf(expf(-fabsf(x)));
}

// BCE terms for one node -> {loss, posOK, negOK, posTot, negTot}
__device__ __forceinline__ void bce5(float x, float pv, float nv, float pw, float* o) {
    float tot = pv + nv;
    o[0] = o[1] = o[2] = o[3] = o[4] = 0.f;
    if (tot > 0.f) {
        float tgt = pv / fmaxf(tot, 1e-9f);
        float bce = pw * tgt * softplusf(-x) + (1.f - tgt) * softplusf(x);
        o[0] = tot * bce;
        o[3] = pv; o[4] = nv;
        if (x >= 0.f) o[1] = pv; else o[2] = nv;
    }
}

// ---------------- prologue: init gather + init-node eval + weight converts ----------------
__device__ void convert_body(const float* __restrict__ W, __half* __restrict__ Wt,
                             int K, int s, int r, int tid) {
    int h = tid >> 7, n = tid & 127;
    const float* Wr = W + ((size_t)r * K + s * 32) * D + h * 128 + n;
    __half loc[32];
#pragma unroll
    for (int k5 = 0; k5 < 32; k5++)
        loc[pos32(k5)] = __float2half_rn(Wr[(size_t)k5 * D]);
    __half* dst = Wt + ((size_t)((r * 2 + h) * (K / 32) + s) * 128 + n) * 32;
    uint4* d4 = (uint4*)dst;
    const uint4* s4 = (const uint4*)loc;
#pragma unroll
    for (int i = 0; i < 4; i++) d4[i] = s4[i];
}

__global__ void __launch_bounds__(256)
prologue(const int* __restrict__ thax, const float* __restrict__ table,
         const float* __restrict__ W1, const float* __restrict__ W2,
         const float* __restrict__ pos_vals, const float* __restrict__ neg_vals,
         const float* __restrict__ eval_w, const float* __restrict__ eval_b,
         const float* __restrict__ pos_weight) {
    int b = blockIdx.x;
    int tid = threadIdx.x;
    if (b < 128) {
        __shared__ float ws[256];
        __shared__ float buf[64 * 64];
        __shared__ float sb[64 * 5];
        const int row_base = b * 64;
        ws[tid] = eval_w[tid];
        __syncthreads();
        const int c = tid & 63;
        const float4 w4 = *(const float4*)(ws + 4 * c);
#pragma unroll
        for (int i = 0; i < 16; i++) {
            int idx = tid + 256 * i;
            int row = idx >> 6;
            int tix = thax[row_base + row];
            float4 v = ((const float4*)(table + (size_t)tix * D))[c];
            int k = c * 4;
            __half* hdst = g_storeh + (size_t)(row_base + row) * D + (k >> 5) * 32;
            int k5 = k & 31;
            *(__half2*)(hdst + pos32(k5))     = __floats2half2_rn(v.x, v.y);
            *(__half2*)(hdst + pos32(k5 + 2)) = __floats2half2_rn(v.z, v.w);
            buf[row * 64 + c] = v.x * w4.x + v.y * w4.y + v.z * w4.z + v.w * w4.w;
        }
        __syncthreads();
        {
            int row = tid >> 2, q = tid & 3;
            float s = 0.f;
#pragma unroll
            for (int j = 0; j < 16; j++) s += buf[row * 64 + q * 16 + j];
            s += __shfl_xor_sync(0xffffffffu, s, 1);
            s += __shfl_xor_sync(0xffffffffu, s, 2);
            if (q == 0) {
                int node = row_base + row;
                float o[5];
                bce5(s + *eval_b, pos_vals[node], neg_vals[node], *pos_weight, o);
#pragma unroll
                for (int cc = 0; cc < 5; cc++) sb[row * 5 + cc] = o[cc];
            }
        }
        __syncthreads();
        if (tid < 5) {
            float t = 0.f;
            for (int i = 0; i < 64; i++) t += sb[i * 5 + tid];
            g_partials[(L * 128 + b) * 5 + tid] = t;
        }
    } else if (b < 128 + 256) {
        int idx = b - 128;
        convert_body(W1, g_W1h, K1, idx & 15, idx >> 4, tid);
    } else {
        int idx = b - 384;
        convert_body(W2, g_W2h, K2, idx & 7, idx >> 3, tid);
    }
}

// ---------------- fused layer kernel + in-epilogue eval (+ final reduce on last layer) ----
__global__ void __launch_bounds__(512, 1)
layer_fused(const float* __restrict__ b1, const float* __restrict__ b2,
            const int* __restrict__ par, int layer,
            const float* __restrict__ pos_vals, const float* __restrict__ neg_vals,
            const float* __restrict__ eval_w, const float* __restrict__ eval_b,
            const float* __restrict__ pos_weight,
            float* __restrict__ out, int out_size) {
    extern __shared__ __half sm[];
    __shared__ __align__(8) uint64_t mbars[4];   // [0,1] B ring, [2] A-p0, [3] A-p1
    __shared__ int is_last;
    __half* smB = sm + OFF_B;
    __half* Hs  = sm;                            // aliases A region
    const uint32_t smAu = smem_to_u32(sm);
    const uint32_t smBu = smem_to_u32(smB);

    const int tid  = threadIdx.x;
    const int lane = tid & 31;
    const int wid  = tid >> 5;
    const int g    = lane >> 2, t4 = lane & 3;
    const int warp_m = wid >> 3, warp_n = wid & 7;   // 2 x 8, warp tile 32x32
    const int bid = blockIdx.x;
    const int m0 = bid * 64;
    const int r  = bid >> 3;

    const __half* W1r = g_W1h + (size_t)(r * 2 * (K1 / 32)) * 4096;
    const __half* W2r = g_W2h + (size_t)(r * 2 * (K2 / 32)) * 4096;

    auto issueB = [&](int s) {
        uint32_t mb = smem_to_u32(&mbars[s & 1]);
        MBARRIER_EXPECT_TX(mb, 65536);
        uint32_t dst = smBu + (uint32_t)((s & 1) * SLOT) * 2u;
        const __half* Wr_;
        int hstride, s32;
        if (s < NS1) { Wr_ = W1r; hstride = K1 / 32; s32 = 4 * s; }
        else         { Wr_ = W2r; hstride = K2 / 32; s32 = 4 * (s - NS1); }
        BULK_G2S(dst,         Wr_ + (size_t)s32 * 4096,             32768, mb);
        BULK_G2S(dst + 32768, Wr_ + (size_t)(hstride + s32) * 4096, 32768, mb);
    };

    if (tid == 0) {
#pragma unroll
        for (int i = 0; i < 4; i++) MBARRIER_INIT(smem_to_u32(&mbars[i]), 1);
        asm volatile("fence.proxy.async.shared::cta;" ::: "memory");
    }
    __syncthreads();

    // A gather, split by parent: p0 (cols 0-255, needed by stages 0-1) first
    if (tid == 0) {
        MBARRIER_EXPECT_TX(smem_to_u32(&mbars[2]), 32768);
        MBARRIER_EXPECT_TX(smem_to_u32(&mbars[3]), 32768);
    }
    __syncthreads();
    if (tid < 128) {
        int p = tid >> 6, row = tid & 63;
        const __half* src = g_storeh + (size_t)par[2 * (m0 + row) + p] * D;
        uint32_t dst = smAu + (uint32_t)(row * AS + p * 256) * 2u;
        BULK_G2S(dst, src, 512, smem_to_u32(&mbars[2 + p]));
    }
    if (tid == 0) { issueB(0); issueB(1); }

    float acc[2][4][4];
#pragma unroll
    for (int mt = 0; mt < 2; mt++)
#pragma unroll
        for (int nt = 0; nt < 4; nt++)
#pragma unroll
            for (int c = 0; c < 4; c++) acc[mt][nt][c] = 0.f;

    auto do_sub = [&](const __half* Arow0, int astr, int koff, const __half* Bsub) {
        uint4 Av[2][2];
#pragma unroll
        for (int mt = 0; mt < 2; mt++) {
            const __half* ab = Arow0 + (warp_m * 32 + mt * 16 + g) * astr + koff + t4 * 8;
            Av[mt][0] = *(const uint4*)ab;
            Av[mt][1] = *(const uint4*)(ab + 8 * astr);
        }
        uint4 Bv[4];
#pragma unroll
        for (int nt = 0; nt < 4; nt++) {
            int cc = (warp_n & 3) * 32 + nt * 8 + g;
            Bv[nt] = *(const uint4*)(Bsub + cc * 32 + t4 * 8);
        }
#pragma unroll
        for (int step = 0; step < 2; step++) {
#pragma unroll
            for (int mt = 0; mt < 2; mt++) {
                uint32_t a0 = step ? Av[mt][0].z : Av[mt][0].x;
                uint32_t a1 = step ? Av[mt][1].z : Av[mt][1].x;
                uint32_t a2 = step ? Av[mt][0].w : Av[mt][0].y;
                uint32_t a3 = step ? Av[mt][1].w : Av[mt][1].y;
#pragma unroll
                for (int nt = 0; nt < 4; nt++) {
                    uint32_t b0 = step ? Bv[nt].z : Bv[nt].x;
                    uint32_t b1r = step ? Bv[nt].w : Bv[nt].y;
                    asm volatile(
                        "mma.sync.aligned.m16n8k16.row.col.f32.f16.f16.f32 "
                        "{%0,%1,%2,%3}, {%4,%5,%6,%7}, {%8,%9}, {%0,%1,%2,%3};"
                        : "+f"(acc[mt][nt][0]), "+f"(acc[mt][nt][1]),
                          "+f"(acc[mt][nt][2]), "+f"(acc[mt][nt][3])
                        : "r"(a0), "r"(a1), "r"(a2), "r"(a3), "r"(b0), "r"(b1r));
                }
            }
        }
    };

    const int hsel = (warp_n >> 2) * 16384;

    // ================= GEMM1 =================
#pragma unroll
    for (int s = 0; s < NS1; s++) {
        if (s == 0) MBARRIER_WAIT_PARITY(smem_to_u32(&mbars[2]), 0);
        if (s == 2) MBARRIER_WAIT_PARITY(smem_to_u32(&mbars[3]), 0);
        MBARRIER_WAIT_PARITY(smem_to_u32(&mbars[s & 1]), (s >> 1) & 1);
        const __half* Bslot = smB + (s & 1) * SLOT + hsel;
#pragma unroll
        for (int sub = 0; sub < 4; sub++)
            do_sub(sm, AS, s * 128 + sub * 32, Bslot + sub * 4096);
        __syncthreads();
        if (tid == 0 && s + 2 < NSTG) issueB(s + 2);
    }

    // ---- H epilogue: bias1 + relu -> Hs ----
    {
        const float* br = b1 + r * D;
#pragma unroll
        for (int mt = 0; mt < 2; mt++) {
            int rA = warp_m * 32 + mt * 16 + g;
#pragma unroll
            for (int nt = 0; nt < 4; nt++) {
                int col = warp_n * 32 + nt * 8 + 2 * t4;
                float bx = br[col], by = br[col + 1];
                float x0 = fmaxf(acc[mt][nt][0] + bx, 0.f);
                float y0 = fmaxf(acc[mt][nt][1] + by, 0.f);
                float x1 = fmaxf(acc[mt][nt][2] + bx, 0.f);
                float y1 = fmaxf(acc[mt][nt][3] + by, 0.f);
                int hoff = (col >> 5) * 32 + pos32(col & 31);
                *(__half2*)(Hs + rA * HS + hoff)       = __floats2half2_rn(x0, y0);
                *(__half2*)(Hs + (rA + 8) * HS + hoff) = __floats2half2_rn(x1, y1);
            }
        }
    }
    __syncthreads();

    // ================= GEMM2 (A = Hs) =================
#pragma unroll
    for (int mt = 0; mt < 2; mt++)
#pragma unroll
        for (int nt = 0; nt < 4; nt++)
#pragma unroll
            for (int c = 0; c < 4; c++) acc[mt][nt][c] = 0.f;

#pragma unroll
    for (int s2 = 0; s2 < NS2; s2++) {
        int gs = NS1 + s2;
        MBARRIER_WAIT_PARITY(smem_to_u32(&mbars[gs & 1]), (gs >> 1) & 1);
        const __half* Bslot = smB + (gs & 1) * SLOT + hsel;
#pragma unroll
        for (int sub = 0; sub < 4; sub++)
            do_sub(Hs, HS, s2 * 128 + sub * 32, Bslot + sub * 4096);
    }

    // ---- C epilogue: bias2 -> g_storeh + per-row logit partials (fp32) ----
    float prA[2] = {0.f, 0.f}, prB[2] = {0.f, 0.f};
    {
        __half* Cbase = g_storeh + (size_t)(N0 + layer * NL) * D;
        const float* br = b2 + r * D;
#pragma unroll
        for (int mt = 0; mt < 2; mt++) {
            int mr0 = m0 + warp_m * 32 + mt * 16 + g;
#pragma unroll
            for (int nt = 0; nt < 4; nt++) {
                int col = warp_n * 32 + nt * 8 + 2 * t4;
                float bx = br[col], by = br[col + 1];
                float x0 = acc[mt][nt][0] + bx, y0 = acc[mt][nt][1] + by;
                float x1 = acc[mt][nt][2] + bx, y1 = acc[mt][nt][3] + by;
                int hoff = (col >> 5) * 32 + pos32(col & 31);
                *(__half2*)(Cbase + (size_t)mr0 * D + hoff)       = __floats2half2_rn(x0, y0);
                *(__half2*)(Cbase + (size_t)(mr0 + 8) * D + hoff) = __floats2half2_rn(x1, y1);
                float2 wp = *(const float2*)(eval_w + col);
                prA[mt] += x0 * wp.x + y0 * wp.y;
                prB[mt] += x1 * wp.x + y1 * wp.y;
            }
        }
    }
#pragma unroll
    for (int mt = 0; mt < 2; mt++) {
        prA[mt] += __shfl_xor_sync(0xffffffffu, prA[mt], 1);
        prA[mt] += __shfl_xor_sync(0xffffffffu, prA[mt], 2);
        prB[mt] += __shfl_xor_sync(0xffffffffu, prB[mt], 1);
        prB[mt] += __shfl_xor_sync(0xffffffffu, prB[mt], 2);
    }
    __syncthreads();                       // all B-slot reads done -> reuse as scratch
    float* sred = (float*)smB;             // 64 rows x 8 warp_n
    float* sbw  = sred + 512;              // 2 warps x 5
    if (t4 == 0) {
#pragma unroll
        for (int mt = 0; mt < 2; mt++) {
            int rA = warp_m * 32 + mt * 16 + g;
            sred[rA * 8 + warp_n]       = prA[mt];
            sred[(rA + 8) * 8 + warp_n] = prB[mt];
        }
    }
    __syncthreads();
    if (tid < 64) {
        float s8 = 0.f;
#pragma unroll
        for (int wn = 0; wn < 8; wn++) s8 += sred[tid * 8 + wn];
        int node = N0 + layer * NL + m0 + tid;
        float o[5];
        bce5(s8 + *eval_b, pos_vals[node], neg_vals[node], *pos_weight, o);
        // warp-level reduce across 32 rows (deterministic shuffle tree)
#pragma unroll
        for (int c = 0; c < 5; c++) {
#pragma unroll
            for (int off = 16; off; off >>= 1)
                o[c] += __shfl_xor_sync(0xffffffffu, o[c], off);
            if (lane == 0) sbw[wid * 5 + c] = o[c];
        }
    }
    __syncthreads();
    if (tid < 5)
        g_partials[(layer * 128 + bid) * 5 + tid] = sbw[tid] + sbw[5 + tid];

    // ---- last layer: final reduce by the last-finishing CTA (deterministic order) ----
    if (layer == L - 1) {
        __threadfence();
        __syncthreads();
        if (tid == 0)
            is_last = (atomicAdd(&g_donecnt, 1) == 127) ? 1 : 0;
        __syncthreads();
        if (is_last && tid < 32) {
            __threadfence();
            float s[5] = {0.f, 0.f, 0.f, 0.f, 0.f};
            for (int i = tid; i < NSLOTS; i += 32) {
                const volatile float* p = g_partials + i * 5;
#pragma unroll
                for (int c = 0; c < 5; c++) s[c] += p[c];
            }
#pragma unroll
            for (int c = 0; c < 5; c++)
#pragma unroll
                for (int off = 16; off; off >>= 1)
                    s[c] += __shfl_xor_sync(0xffffffffu, s[c], off);
            if (tid == 0) {
                float pos_rate = (s[3] > 0.f) ? s[1] / fmaxf(s[3], 1e-9f) : 1.f;
                float neg_rate = (s[4] > 0.f) ? s[2] / fmaxf(s[4], 1e-9f) : 1.f;
                if (out_size >= 1) out[0] = s[0];
                if (out_size >= 2) out[1] = pos_rate;
                if (out_size >= 3) out[2] = neg_rate;
                g_donecnt = 0;               // self-clean for next graph replay
            }
        }
    }
}

// ---------------- launch ----------------
extern "C" void kernel_launch(void* const* d_in, const int* in_sizes, int n_in,
                              void* d_out, int out_size) {
    const int*   thax       = (const int*)  d_in[0];
    const int*   par_idx    = (const int*)  d_in[1];
    const float* pos_vals   = (const float*)d_in[2];
    const float* neg_vals   = (const float*)d_in[3];
    const float* init_table = (const float*)d_in[4];
    const float* W1         = (const float*)d_in[5];
    const float* b1         = (const float*)d_in[6];
    const float* W2         = (const float*)d_in[7];
    const float* b2         = (const float*)d_in[8];
    const float* eval_w     = (const float*)d_in[9];
    const float* eval_b     = (const float*)d_in[10];
    const float* pos_weight = (const float*)d_in[11];
    float* out = (float*)d_out;

    cudaFuncSetAttribute(layer_fused,
                         cudaFuncAttributeMaxDynamicSharedMemorySize, SMEM_BYTES);

    prologue<<<128 + 256 + 128, 256>>>(thax, init_table, W1, W2,
                                       pos_vals, neg_vals, eval_w, eval_b, pos_weight);

    for (int l = 0; l < L; l++) {
        layer_fused<<<NL / 64, 512, SMEM_BYTES>>>(
            b1, b2, par_idx + (size_t)l * NL * 2, l,
            pos_vals, neg_vals, eval_w, eval_b, pos_weight, out, out_size);
    }
}

// round 16
// speedup vs baseline: 1.0208x; 1.0208x over previous
#include <cuda_runtime.h>
#include <cuda_fp16.h>
#include <math.h>
#include <cstdint>

#define D      256
#define R      16
#define N0     8192
#define L      6
#define NL     8192
#define TOTAL  (N0 + L * NL)   // 57344

#define K1 512
#define K2 256
#define NS1  4                 // K1/128 superstages
#define NS2  2                 // K2/128
#define NSTG (NS1 + NS2)       // 6

#define NSLOTS (L * 128 + 128) // 896 partial slots

// smem layout (halfs)
#define AS     544             // A row stride (K1+32): conflict-free LDS.128 phases
#define HS     288             // H row stride (aliases A region)
#define OFF_B  (64 * AS)                  // 34816 halfs
#define SLOT   32768                      // 64KB superstage: [h(2)][sub(4)][128n][32k]
#define SMEM_HALFS (OFF_B + 2 * SLOT)     // 100352
#define SMEM_BYTES (SMEM_HALFS * 2)       // 200704

// ---------------- scratch (device globals; no allocation) ----------------
__device__ __half g_storeh[(size_t)TOTAL * D];    // fp16 k-interleaved embeddings
__device__ __half g_W1h[(size_t)R * D * K1];      // [r][h(2)][s32(16)][128n][32k]
__device__ __half g_W2h[(size_t)R * D * K2];      // [r][h(2)][s32(8)][128n][32k]
__device__ float  g_partials[NSLOTS * 5];         // fully rewritten each run

__device__ __forceinline__ uint32_t smem_to_u32(const void* p) {
    uint32_t a;
    asm("{ .reg .u64 t; cvta.to.shared.u64 t, %1; cvt.u32.u64 %0, t; }" : "=r"(a) : "l"(p));
    return a;
}

__device__ __forceinline__ int pos32(int k5) {
    return ((k5 >> 1) & 3) * 8 + (k5 >> 4) * 4 + ((k5 >> 3) & 1) * 2 + (k5 & 1);
}

#define MBARRIER_INIT(mbar, cnt) \
    asm volatile("mbarrier.init.shared.b64 [%0], %1;" \
                 :: "r"((uint32_t)(mbar)), "r"((uint32_t)(cnt)) : "memory")
#define MBARRIER_EXPECT_TX(mbar, bytes) \
    asm volatile("mbarrier.arrive.expect_tx.shared.b64 _, [%0], %1;" \
                 :: "r"((uint32_t)(mbar)), "r"((uint32_t)(bytes)) : "memory")
#define MBARRIER_WAIT_PARITY(mbar_a, par) do { \
    uint32_t _m = (uint32_t)(mbar_a), _p = (uint32_t)(par), _d; \
    asm volatile("{\n\t.reg .pred p;\n\t" \
        "mbarrier.try_wait.parity.acquire.cta.shared::cta.b64 p, [%1], %2;\n\t" \
        "selp.b32 %0, 1, 0, p;\n\t}" : "=r"(_d) : "r"(_m), "r"(_p) : "memory"); \
    if (!_d) { \
        asm volatile("{\n\t.reg .pred P1;\n\t" \
            "WL_%=:\n\t" \
            "mbarrier.try_wait.parity.acquire.cta.shared::cta.b64 P1, [%0], %1, 0x989680;\n\t" \
            "@P1 bra.uni WD_%=;\n\t" \
            "bra.uni WL_%=;\n\t" \
            "WD_%=:\n\t}" :: "r"(_m), "r"(_p) : "memory"); \
    } \
} while (0)
#define BULK_G2S(dst_u32, src_ptr, bytes, mbar_u32) \
    asm volatile("cp.async.bulk.shared::cta.global.mbarrier::complete_tx::bytes " \
                 "[%0], [%1], %2, [%3];" \
                 :: "r"(dst_u32), "l"(src_ptr), "r"((uint32_t)(bytes)), \
                    "r"(mbar_u32) : "memory")

__device__ __forceinline__ float softplusf(float x) {
    return fmaxf(x, 0.f) + log1pf(expf(-fabsf(x)));
}

// BCE terms for one node -> 5 partials {loss, posOK, negOK, posTot, negTot}
__device__ __forceinline__ void bce5(float x, float pv, float nv, float pw, float* o) {
    float tot = pv + nv;
    o[0] = o[1] = o[2] = o[3] = o[4] = 0.f;
    if (tot > 0.f) {
        float tgt = pv / fmaxf(tot, 1e-9f);
        float bce = pw * tgt * softplusf(-x) + (1.f - tgt) * softplusf(x);
        o[0] = tot * bce;
        o[3] = pv; o[4] = nv;
        if (x >= 0.f) o[1] = pv; else o[2] = nv;
    }
}

// ---------------- prologue: init gather + init-node eval + weight converts ----------------
__device__ void convert_body(const float* __restrict__ W, __half* __restrict__ Wt,
                             int K, int s, int r, int tid) {
    int h = tid >> 7, n = tid & 127;
    const float* Wr = W + ((size_t)r * K + s * 32) * D + h * 128 + n;
    __half loc[32];
#pragma unroll
    for (int k5 = 0; k5 < 32; k5++)
        loc[pos32(k5)] = __float2half_rn(Wr[(size_t)k5 * D]);
    __half* dst = Wt + ((size_t)((r * 2 + h) * (K / 32) + s) * 128 + n) * 32;
    uint4* d4 = (uint4*)dst;
    const uint4* s4 = (const uint4*)loc;
#pragma unroll
    for (int i = 0; i < 4; i++) d4[i] = s4[i];
}

__global__ void __launch_bounds__(256)
prologue(const int* __restrict__ thax, const float* __restrict__ table,
         const float* __restrict__ W1, const float* __restrict__ W2,
         const float* __restrict__ pos_vals, const float* __restrict__ neg_vals,
         const float* __restrict__ eval_w, const float* __restrict__ eval_b,
         const float* __restrict__ pos_weight) {
    int b = blockIdx.x;
    int tid = threadIdx.x;
    if (b < 128) {
        // gather 64 init rows + eval them
        __shared__ float ws[256];
        __shared__ float buf[64 * 64];     // per (row, c-chunk) partial dots
        __shared__ float sb[64 * 5];
        const int row_base = b * 64;
        ws[tid] = eval_w[tid];
        __syncthreads();
        const int c = tid & 63;            // fixed float4-chunk per thread
        const float4 w4 = *(const float4*)(ws + 4 * c);
#pragma unroll
        for (int i = 0; i < 16; i++) {
            int idx = tid + 256 * i;
            int row = idx >> 6;            // 0..63
            int tix = thax[row_base + row];
            float4 v = ((const float4*)(table + (size_t)tix * D))[c];
            int k = c * 4;
            __half* hdst = g_storeh + (size_t)(row_base + row) * D + (k >> 5) * 32;
            int k5 = k & 31;
            *(__half2*)(hdst + pos32(k5))     = __floats2half2_rn(v.x, v.y);
            *(__half2*)(hdst + pos32(k5 + 2)) = __floats2half2_rn(v.z, v.w);
            buf[row * 64 + c] = v.x * w4.x + v.y * w4.y + v.z * w4.z + v.w * w4.w;
        }
        __syncthreads();
        {
            int row = tid >> 2, q = tid & 3;
            float s = 0.f;
#pragma unroll
            for (int j = 0; j < 16; j++) s += buf[row * 64 + q * 16 + j];
            s += __shfl_xor_sync(0xffffffffu, s, 1);
            s += __shfl_xor_sync(0xffffffffu, s, 2);
            if (q == 0) {
                int node = row_base + row;
                float o[5];
                bce5(s + *eval_b, pos_vals[node], neg_vals[node], *pos_weight, o);
#pragma unroll
                for (int cc = 0; cc < 5; cc++) sb[row * 5 + cc] = o[cc];
            }
        }
        __syncthreads();
        if (tid < 5) {
            float t = 0.f;
            for (int i = 0; i < 64; i++) t += sb[i * 5 + tid];
            g_partials[(L * 128 + b) * 5 + tid] = t;
        }
    } else if (b < 128 + 256) {
        int idx = b - 128;
        convert_body(W1, g_W1h, K1, idx & 15, idx >> 4, tid);
    } else {
        int idx = b - 384;
        convert_body(W2, g_W2h, K2, idx & 7, idx >> 3, tid);
    }
}

// ---------------- fused layer kernel (R14 structure) + split A-gather ----------------
__global__ void __launch_bounds__(512, 1)
layer_fused(const float* __restrict__ b1, const float* __restrict__ b2,
            const int* __restrict__ par, int layer,
            const float* __restrict__ pos_vals, const float* __restrict__ neg_vals,
            const float* __restrict__ eval_w, const float* __restrict__ eval_b,
            const float* __restrict__ pos_weight) {
    extern __shared__ __half sm[];
    __shared__ __align__(8) uint64_t mbars[4];   // [0,1] B ring, [2] A-p0, [3] A-p1
    __half* smB = sm + OFF_B;
    __half* Hs  = sm;                            // aliases A region
    const uint32_t smAu = smem_to_u32(sm);
    const uint32_t smBu = smem_to_u32(smB);

    const int tid  = threadIdx.x;
    const int lane = tid & 31;
    const int wid  = tid >> 5;
    const int g    = lane >> 2, t4 = lane & 3;
    const int warp_m = wid >> 3, warp_n = wid & 7;   // 2 x 8, warp tile 32x32
    const int bid = blockIdx.x;
    const int m0 = bid * 64;
    const int r  = bid >> 3;

    const __half* W1r = g_W1h + (size_t)(r * 2 * (K1 / 32)) * 4096;
    const __half* W2r = g_W2h + (size_t)(r * 2 * (K2 / 32)) * 4096;

    auto issueB = [&](int s) {
        uint32_t mb = smem_to_u32(&mbars[s & 1]);
        MBARRIER_EXPECT_TX(mb, 65536);
        uint32_t dst = smBu + (uint32_t)((s & 1) * SLOT) * 2u;
        const __half* Wr_;
        int hstride, s32;
        if (s < NS1) { Wr_ = W1r; hstride = K1 / 32; s32 = 4 * s; }
        else         { Wr_ = W2r; hstride = K2 / 32; s32 = 4 * (s - NS1); }
        BULK_G2S(dst,         Wr_ + (size_t)s32 * 4096,             32768, mb);
        BULK_G2S(dst + 32768, Wr_ + (size_t)(hstride + s32) * 4096, 32768, mb);
    };

    if (tid == 0) {
#pragma unroll
        for (int i = 0; i < 4; i++) MBARRIER_INIT(smem_to_u32(&mbars[i]), 1);
        asm volatile("fence.proxy.async.shared::cta;" ::: "memory");
    }
    __syncthreads();

    // A gather, split by parent: p0 (cols 0-255, feeds stages 0-1) completes first
    if (tid == 0) {
        MBARRIER_EXPECT_TX(smem_to_u32(&mbars[2]), 32768);
        MBARRIER_EXPECT_TX(smem_to_u32(&mbars[3]), 32768);
    }
    __syncthreads();
    if (tid < 128) {
        int p = tid >> 6, row = tid & 63;
        const __half* src = g_storeh + (size_t)par[2 * (m0 + row) + p] * D;
        uint32_t dst = smAu + (uint32_t)(row * AS + p * 256) * 2u;
        BULK_G2S(dst, src, 512, smem_to_u32(&mbars[2 + p]));
    }
    if (tid == 0) { issueB(0); issueB(1); }

    float acc[2][4][4];
#pragma unroll
    for (int mt = 0; mt < 2; mt++)
#pragma unroll
        for (int nt = 0; nt < 4; nt++)
#pragma unroll
            for (int c = 0; c < 4; c++) acc[mt][nt][c] = 0.f;

    auto do_sub = [&](const __half* Arow0, int astr, int koff, const __half* Bsub) {
        uint4 Av[2][2];
#pragma unroll
        for (int mt = 0; mt < 2; mt++) {
            const __half* ab = Arow0 + (warp_m * 32 + mt * 16 + g) * astr + koff + t4 * 8;
            Av[mt][0] = *(const uint4*)ab;
            Av[mt][1] = *(const uint4*)(ab + 8 * astr);
        }
        uint4 Bv[4];
#pragma unroll
        for (int nt = 0; nt < 4; nt++) {
            int cc = (warp_n & 3) * 32 + nt * 8 + g;
            Bv[nt] = *(const uint4*)(Bsub + cc * 32 + t4 * 8);
        }
#pragma unroll
        for (int step = 0; step < 2; step++) {
#pragma unroll
            for (int mt = 0; mt < 2; mt++) {
                uint32_t a0 = step ? Av[mt][0].z : Av[mt][0].x;
                uint32_t a1 = step ? Av[mt][1].z : Av[mt][1].x;
                uint32_t a2 = step ? Av[mt][0].w : Av[mt][0].y;
                uint32_t a3 = step ? Av[mt][1].w : Av[mt][1].y;
#pragma unroll
                for (int nt = 0; nt < 4; nt++) {
                    uint32_t b0 = step ? Bv[nt].z : Bv[nt].x;
                    uint32_t b1r = step ? Bv[nt].w : Bv[nt].y;
                    asm volatile(
                        "mma.sync.aligned.m16n8k16.row.col.f32.f16.f16.f32 "
                        "{%0,%1,%2,%3}, {%4,%5,%6,%7}, {%8,%9}, {%0,%1,%2,%3};"
                        : "+f"(acc[mt][nt][0]), "+f"(acc[mt][nt][1]),
                          "+f"(acc[mt][nt][2]), "+f"(acc[mt][nt][3])
                        : "r"(a0), "r"(a1), "r"(a2), "r"(a3), "r"(b0), "r"(b1r));
                }
            }
        }
    };

    const int hsel = (warp_n >> 2) * 16384;

    // ================= GEMM1 =================
#pragma unroll
    for (int s = 0; s < NS1; s++) {
        if (s == 0) MBARRIER_WAIT_PARITY(smem_to_u32(&mbars[2]), 0);
        if (s == 2) MBARRIER_WAIT_PARITY(smem_to_u32(&mbars[3]), 0);
        MBARRIER_WAIT_PARITY(smem_to_u32(&mbars[s & 1]), (s >> 1) & 1);
        const __half* Bslot = smB + (s & 1) * SLOT + hsel;
#pragma unroll
        for (int sub = 0; sub < 4; sub++)
            do_sub(sm, AS, s * 128 + sub * 32, Bslot + sub * 4096);
        __syncthreads();
        if (tid == 0 && s + 2 < NSTG) issueB(s + 2);
    }

    // ---- H epilogue: bias1 + relu -> Hs ----
    {
        const float* br = b1 + r * D;
#pragma unroll
        for (int mt = 0; mt < 2; mt++) {
            int rA = warp_m * 32 + mt * 16 + g;
#pragma unroll
            for (int nt = 0; nt < 4; nt++) {
                int col = warp_n * 32 + nt * 8 + 2 * t4;
                float bx = br[col], by = br[col + 1];
                float x0 = fmaxf(acc[mt][nt][0] + bx, 0.f);
                float y0 = fmaxf(acc[mt][nt][1] + by, 0.f);
                float x1 = fmaxf(acc[mt][nt][2] + bx, 0.f);
                float y1 = fmaxf(acc[mt][nt][3] + by, 0.f);
                int hoff = (col >> 5) * 32 + pos32(col & 31);
                *(__half2*)(Hs + rA * HS + hoff)       = __floats2half2_rn(x0, y0);
                *(__half2*)(Hs + (rA + 8) * HS + hoff) = __floats2half2_rn(x1, y1);
            }
        }
    }
    __syncthreads();

    // ================= GEMM2 (A = Hs) =================
#pragma unroll
    for (int mt = 0; mt < 2; mt++)
#pragma unroll
        for (int nt = 0; nt < 4; nt++)
#pragma unroll
            for (int c = 0; c < 4; c++) acc[mt][nt][c] = 0.f;

#pragma unroll
    for (int s2 = 0; s2 < NS2; s2++) {
        int gs = NS1 + s2;
        MBARRIER_WAIT_PARITY(smem_to_u32(&mbars[gs & 1]), (gs >> 1) & 1);
        const __half* Bslot = smB + (gs & 1) * SLOT + hsel;
#pragma unroll
        for (int sub = 0; sub < 4; sub++)
            do_sub(Hs, HS, s2 * 128 + sub * 32, Bslot + sub * 4096);
    }

    // ---- C epilogue: bias2 -> g_storeh + per-row logit partials (fp32) ----
    float prA[2] = {0.f, 0.f}, prB[2] = {0.f, 0.f};
    {
        __half* Cbase = g_storeh + (size_t)(N0 + layer * NL) * D;
        const float* br = b2 + r * D;
#pragma unroll
        for (int mt = 0; mt < 2; mt++) {
            int mr0 = m0 + warp_m * 32 + mt * 16 + g;
#pragma unroll
            for (int nt = 0; nt < 4; nt++) {
                int col = warp_n * 32 + nt * 8 + 2 * t4;
                float bx = br[col], by = br[col + 1];
                float x0 = acc[mt][nt][0] + bx, y0 = acc[mt][nt][1] + by;
                float x1 = acc[mt][nt][2] + bx, y1 = acc[mt][nt][3] + by;
                int hoff = (col >> 5) * 32 + pos32(col & 31);
                *(__half2*)(Cbase + (size_t)mr0 * D + hoff)       = __floats2half2_rn(x0, y0);
                *(__half2*)(Cbase + (size_t)(mr0 + 8) * D + hoff) = __floats2half2_rn(x1, y1);
                float2 wp = *(const float2*)(eval_w + col);
                prA[mt] += x0 * wp.x + y0 * wp.y;
                prB[mt] += x1 * wp.x + y1 * wp.y;
            }
        }
    }
    // reduce logit partials across t4 lanes (lanes g*4+t4 share the row)
#pragma unroll
    for (int mt = 0; mt < 2; mt++) {
        prA[mt] += __shfl_xor_sync(0xffffffffu, prA[mt], 1);
        prA[mt] += __shfl_xor_sync(0xffffffffu, prA[mt], 2);
        prB[mt] += __shfl_xor_sync(0xffffffffu, prB[mt], 1);
        prB[mt] += __shfl_xor_sync(0xffffffffu, prB[mt], 2);
    }
    __syncthreads();                       // all B-slot reads done -> reuse as scratch
    float* sred = (float*)smB;             // 64 rows x 8 warp_n
    float* sb   = sred + 512;              // 64 rows x 5
    if (t4 == 0) {
#pragma unroll
        for (int mt = 0; mt < 2; mt++) {
            int rA = warp_m * 32 + mt * 16 + g;
            sred[rA * 8 + warp_n]       = prA[mt];
            sred[(rA + 8) * 8 + warp_n] = prB[mt];
        }
    }
    __syncthreads();
    if (tid < 64) {
        float s8 = 0.f;
#pragma unroll
        for (int wn = 0; wn < 8; wn++) s8 += sred[tid * 8 + wn];
        int node = N0 + layer * NL + m0 + tid;
        float o[5];
        bce5(s8 + *eval_b, pos_vals[node], neg_vals[node], *pos_weight, o);
#pragma unroll
        for (int c = 0; c < 5; c++) sb[tid * 5 + c] = o[c];
    }
    __syncthreads();
    if (tid < 5) {
        float t = 0.f;
        for (int i = 0; i < 64; i++) t += sb[i * 5 + tid];
        g_partials[(layer * 128 + bid) * 5 + tid] = t;
    }
}

// ---------------- final reduce: 896 slots x 5, deterministic ----------------
__global__ void final_reduce(float* __restrict__ out, int out_size) {
    const int lane = threadIdx.x;
    float s[5] = {0.f, 0.f, 0.f, 0.f, 0.f};
    for (int i = lane; i < NSLOTS; i += 32)
#pragma unroll
        for (int c = 0; c < 5; c++) s[c] += g_partials[i * 5 + c];
#pragma unroll
    for (int c = 0; c < 5; c++)
#pragma unroll
        for (int off = 16; off; off >>= 1)
            s[c] += __shfl_xor_sync(0xffffffffu, s[c], off);
    if (lane == 0) {
        float pos_rate = (s[3] > 0.f) ? s[1] / fmaxf(s[3], 1e-9f) : 1.f;
        float neg_rate = (s[4] > 0.f) ? s[2] / fmaxf(s[4], 1e-9f) : 1.f;
        if (out_size >= 1) out[0] = s[0];
        if (out_size >= 2) out[1] = pos_rate;
        if (out_size >= 3) out[2] = neg_rate;
    }
}

// ---------------- launch ----------------
extern "C" void kernel_launch(void* const* d_in, const int* in_sizes, int n_in,
                              void* d_out, int out_size) {
    const int*   thax       = (const int*)  d_in[0];
    const int*   par_idx    = (const int*)  d_in[1];
    const float* pos_vals   = (const float*)d_in[2];
    const float* neg_vals   = (const float*)d_in[3];
    const float* init_table = (const float*)d_in[4];
    const float* W1         = (const float*)d_in[5];
    const float* b1         = (const float*)d_in[6];
    const float* W2         = (const float*)d_in[7];
    const float* b2         = (const float*)d_in[8];
    const float* eval_w     = (const float*)d_in[9];
    const float* eval_b     = (const float*)d_in[10];
    const float* pos_weight = (const float*)d_in[11];
    float* out = (float*)d_out;

    cudaFuncSetAttribute(layer_fused,
                         cudaFuncAttributeMaxDynamicSharedMemorySize, SMEM_BYTES);

    prologue<<<128 + 256 + 128, 256>>>(thax, init_table, W1, W2,
                                       pos_vals, neg_vals, eval_w, eval_b, pos_weight);

    for (int l = 0; l < L; l++) {
        layer_fused<<<NL / 64, 512, SMEM_BYTES>>>(
            b1, b2, par_idx + (size_t)l * NL * 2, l,
            pos_vals, neg_vals, eval_w, eval_b, pos_weight);
    }

    final_reduce<<<1, 32>>>(out, out_size);
}

// round 17
// speedup vs baseline: 1.0543x; 1.0328x over previous
#include <cuda_runtime.h>
#include <cuda_fp16.h>
#include <math.h>
#include <cstdint>

#define D      256
#define R      16
#define N0     8192
#define L      6
#define NL     8192
#define TOTAL  (N0 + L * NL)   // 57344

#define K1 512
#define K2 256
#define NS1  4                 // K1/128 superstages
#define NS2  2                 // K2/128
#define NSTG (NS1 + NS2)       // 6

#define NSLOTS (L * 128 + 128) // 896 partial slots

// smem layout (halfs)
#define AS     544             // A row stride (K1+32): conflict-free LDS.128 phases
#define HS     288             // H row stride (aliases A region)
#define OFF_B  (64 * AS)                  // 34816 halfs
#define SLOT   32768                      // 64KB superstage: [h(2)][sub(4)][128n][32k]
#define SMEM_HALFS (OFF_B + 2 * SLOT)     // 100352
#define SMEM_BYTES (SMEM_HALFS * 2)       // 200704

// ---------------- scratch (device globals; no allocation) ----------------
__device__ __half g_storeh[(size_t)TOTAL * D];    // fp16 k-interleaved embeddings
__device__ __half g_W1h[(size_t)R * D * K1];      // [r][h(2)][s32(16)][128n][32k]
__device__ __half g_W2h[(size_t)R * D * K2];      // [r][h(2)][s32(8)][128n][32k]
__device__ float  g_partials[NSLOTS * 5];         // fully rewritten each run

__device__ __forceinline__ uint32_t smem_to_u32(const void* p) {
    uint32_t a;
    asm("{ .reg .u64 t; cvta.to.shared.u64 t, %1; cvt.u32.u64 %0, t; }" : "=r"(a) : "l"(p));
    return a;
}

__device__ __forceinline__ int pos32(int k5) {
    return ((k5 >> 1) & 3) * 8 + (k5 >> 4) * 4 + ((k5 >> 3) & 1) * 2 + (k5 & 1);
}

#define MBARRIER_INIT(mbar, cnt) \
    asm volatile("mbarrier.init.shared.b64 [%0], %1;" \
                 :: "r"((uint32_t)(mbar)), "r"((uint32_t)(cnt)) : "memory")
#define MBARRIER_EXPECT_TX(mbar, bytes) \
    asm volatile("mbarrier.arrive.expect_tx.shared.b64 _, [%0], %1;" \
                 :: "r"((uint32_t)(mbar)), "r"((uint32_t)(bytes)) : "memory")
#define MBARRIER_WAIT_PARITY(mbar_a, par) do { \
    uint32_t _m = (uint32_t)(mbar_a), _p = (uint32_t)(par), _d; \
    asm volatile("{\n\t.reg .pred p;\n\t" \
        "mbarrier.try_wait.parity.acquire.cta.shared::cta.b64 p, [%1], %2;\n\t" \
        "selp.b32 %0, 1, 0, p;\n\t}" : "=r"(_d) : "r"(_m), "r"(_p) : "memory"); \
    if (!_d) { \
        asm volatile("{\n\t.reg .pred P1;\n\t" \
            "WL_%=:\n\t" \
            "mbarrier.try_wait.parity.acquire.cta.shared::cta.b64 P1, [%0], %1, 0x989680;\n\t" \
            "@P1 bra.uni WD_%=;\n\t" \
            "bra.uni WL_%=;\n\t" \
            "WD_%=:\n\t}" :: "r"(_m), "r"(_p) : "memory"); \
    } \
} while (0)
#define BULK_G2S(dst_u32, src_ptr, bytes, mbar_u32) \
    asm volatile("cp.async.bulk.shared::cta.global.mbarrier::complete_tx::bytes " \
                 "[%0], [%1], %2, [%3];" \
                 :: "r"(dst_u32), "l"(src_ptr), "r"((uint32_t)(bytes)), \
                    "r"(mbar_u32) : "memory")
#define GRIDDEP_WAIT()   asm volatile("griddepcontrol.wait;" ::: "memory")
#define GRIDDEP_LAUNCH() asm volatile("griddepcontrol.launch_dependents;")

__device__ __forceinline__ float softplusf(float x) {
    return fmaxf(x, 0.f) + log1pf(expf(-fabsf(x)));
}

// BCE terms for one node -> 5 partials {loss, posOK, negOK, posTot, negTot}
__device__ __forceinline__ void bce5(float x, float pv, float nv, float pw, float* o) {
    float tot = pv + nv;
    o[0] = o[1] = o[2] = o[3] = o[4] = 0.f;
    if (tot > 0.f) {
        float tgt = pv / fmaxf(tot, 1e-9f);
        float bce = pw * tgt * softplusf(-x) + (1.f - tgt) * softplusf(x);
        o[0] = tot * bce;
        o[3] = pv; o[4] = nv;
        if (x >= 0.f) o[1] = pv; else o[2] = nv;
    }
}

// ---------------- prologue: init gather + init-node eval + weight converts ----------------
__device__ void convert_body(const float* __restrict__ W, __half* __restrict__ Wt,
                             int K, int s, int r, int tid) {
    int h = tid >> 7, n = tid & 127;
    const float* Wr = W + ((size_t)r * K + s * 32) * D + h * 128 + n;
    __half loc[32];
#pragma unroll
    for (int k5 = 0; k5 < 32; k5++)
        loc[pos32(k5)] = __float2half_rn(Wr[(size_t)k5 * D]);
    __half* dst = Wt + ((size_t)((r * 2 + h) * (K / 32) + s) * 128 + n) * 32;
    uint4* d4 = (uint4*)dst;
    const uint4* s4 = (const uint4*)loc;
#pragma unroll
    for (int i = 0; i < 4; i++) d4[i] = s4[i];
}

__global__ void __launch_bounds__(256)
prologue(const int* __restrict__ thax, const float* __restrict__ table,
         const float* __restrict__ W1, const float* __restrict__ W2,
         const float* __restrict__ pos_vals, const float* __restrict__ neg_vals,
         const float* __restrict__ eval_w, const float* __restrict__ eval_b,
         const float* __restrict__ pos_weight) {
    int b = blockIdx.x;
    int tid = threadIdx.x;
    if (b < 128) {
        // gather 64 init rows + eval them
        __shared__ float ws[256];
        __shared__ float buf[64 * 64];     // per (row, c-chunk) partial dots
        __shared__ float sb[64 * 5];
        const int row_base = b * 64;
        ws[tid] = eval_w[tid];
        __syncthreads();
        const int c = tid & 63;            // fixed float4-chunk per thread
        const float4 w4 = *(const float4*)(ws + 4 * c);
#pragma unroll
        for (int i = 0; i < 16; i++) {
            int idx = tid + 256 * i;
            int row = idx >> 6;            // 0..63
            int tix = thax[row_base + row];
            float4 v = ((const float4*)(table + (size_t)tix * D))[c];
            int k = c * 4;
            __half* hdst = g_storeh + (size_t)(row_base + row) * D + (k >> 5) * 32;
            int k5 = k & 31;
            *(__half2*)(hdst + pos32(k5))     = __floats2half2_rn(v.x, v.y);
            *(__half2*)(hdst + pos32(k5 + 2)) = __floats2half2_rn(v.z, v.w);
            buf[row * 64 + c] = v.x * w4.x + v.y * w4.y + v.z * w4.z + v.w * w4.w;
        }
        __syncthreads();
        {
            int row = tid >> 2, q = tid & 3;
            float s = 0.f;
#pragma unroll
            for (int j = 0; j < 16; j++) s += buf[row * 64 + q * 16 + j];
            s += __shfl_xor_sync(0xffffffffu, s, 1);
            s += __shfl_xor_sync(0xffffffffu, s, 2);
            if (q == 0) {
                int node = row_base + row;
                float o[5];
                bce5(s + *eval_b, pos_vals[node], neg_vals[node], *pos_weight, o);
#pragma unroll
                for (int cc = 0; cc < 5; cc++) sb[row * 5 + cc] = o[cc];
            }
        }
        __syncthreads();
        if (tid < 5) {
            float t = 0.f;
            for (int i = 0; i < 64; i++) t += sb[i * 5 + tid];
            g_partials[(L * 128 + b) * 5 + tid] = t;
        }
    } else if (b < 128 + 256) {
        int idx = b - 128;
        convert_body(W1, g_W1h, K1, idx & 15, idx >> 4, tid);
    } else {
        int idx = b - 384;
        convert_body(W2, g_W2h, K2, idx & 7, idx >> 3, tid);
    }
}

// ---------------- fused layer kernel (R14) + PDL overlap ----------------
__global__ void __launch_bounds__(512, 1)
layer_fused(const float* __restrict__ b1, const float* __restrict__ b2,
            const int* __restrict__ par, int layer,
            const float* __restrict__ pos_vals, const float* __restrict__ neg_vals,
            const float* __restrict__ eval_w, const float* __restrict__ eval_b,
            const float* __restrict__ pos_weight) {
    extern __shared__ __half sm[];
    __shared__ __align__(8) uint64_t mbars[3];   // [0,1] B ring, [2] A
    __half* smB = sm + OFF_B;
    __half* Hs  = sm;                            // aliases A region
    const uint32_t smAu = smem_to_u32(sm);
    const uint32_t smBu = smem_to_u32(smB);
    const uint32_t mbarA = smem_to_u32(&mbars[2]);

    const int tid  = threadIdx.x;
    const int lane = tid & 31;
    const int wid  = tid >> 5;
    const int g    = lane >> 2, t4 = lane & 3;
    const int warp_m = wid >> 3, warp_n = wid & 7;   // 2 x 8, warp tile 32x32
    const int bid = blockIdx.x;
    const int m0 = bid * 64;
    const int r  = bid >> 3;

    const __half* W1r = g_W1h + (size_t)(r * 2 * (K1 / 32)) * 4096;
    const __half* W2r = g_W2h + (size_t)(r * 2 * (K2 / 32)) * 4096;

    auto issueB = [&](int s) {
        uint32_t mb = smem_to_u32(&mbars[s & 1]);
        MBARRIER_EXPECT_TX(mb, 65536);
        uint32_t dst = smBu + (uint32_t)((s & 1) * SLOT) * 2u;
        const __half* Wr_;
        int hstride, s32;
        if (s < NS1) { Wr_ = W1r; hstride = K1 / 32; s32 = 4 * s; }
        else         { Wr_ = W2r; hstride = K2 / 32; s32 = 4 * (s - NS1); }
        BULK_G2S(dst,         Wr_ + (size_t)s32 * 4096,             32768, mb);
        BULK_G2S(dst + 32768, Wr_ + (size_t)(hstride + s32) * 4096, 32768, mb);
    };

    // ---- predecessor-independent prologue (runs during prior layer's tail) ----
    if (tid == 0) {
#pragma unroll
        for (int i = 0; i < 3; i++) MBARRIER_INIT(smem_to_u32(&mbars[i]), 1);
        asm volatile("fence.proxy.async.shared::cta;" ::: "memory");
    }
    __syncthreads();
    if (tid == 0) {
        issueB(0); issueB(1);                 // weights: independent of prior layer
        MBARRIER_EXPECT_TX(mbarA, 64 * 1024);
    }
    __syncthreads();

    // ---- wait for predecessor's g_storeh writes, then A-gather ----
    GRIDDEP_WAIT();
    if (tid < 128) {
        int row = tid >> 1, p = tid & 1;
        const __half* src = g_storeh + (size_t)par[2 * (m0 + row) + p] * D;
        BULK_G2S(smAu + (uint32_t)(row * AS + p * 256) * 2u, src, 512, mbarA);
    }

    float acc[2][4][4];
#pragma unroll
    for (int mt = 0; mt < 2; mt++)
#pragma unroll
        for (int nt = 0; nt < 4; nt++)
#pragma unroll
            for (int c = 0; c < 4; c++) acc[mt][nt][c] = 0.f;

    auto do_sub = [&](const __half* Arow0, int astr, int koff, const __half* Bsub) {
        uint4 Av[2][2];
#pragma unroll
        for (int mt = 0; mt < 2; mt++) {
            const __half* ab = Arow0 + (warp_m * 32 + mt * 16 + g) * astr + koff + t4 * 8;
            Av[mt][0] = *(const uint4*)ab;
            Av[mt][1] = *(const uint4*)(ab + 8 * astr);
        }
        uint4 Bv[4];
#pragma unroll
        for (int nt = 0; nt < 4; nt++) {
            int cc = (warp_n & 3) * 32 + nt * 8 + g;
            Bv[nt] = *(const uint4*)(Bsub + cc * 32 + t4 * 8);
        }
#pragma unroll
        for (int step = 0; step < 2; step++) {
#pragma unroll
            for (int mt = 0; mt < 2; mt++) {
                uint32_t a0 = step ? Av[mt][0].z : Av[mt][0].x;
                uint32_t a1 = step ? Av[mt][1].z : Av[mt][1].x;
                uint32_t a2 = step ? Av[mt][0].w : Av[mt][0].y;
                uint32_t a3 = step ? Av[mt][1].w : Av[mt][1].y;
#pragma unroll
                for (int nt = 0; nt < 4; nt++) {
                    uint32_t b0 = step ? Bv[nt].z : Bv[nt].x;
                    uint32_t b1r = step ? Bv[nt].w : Bv[nt].y;
                    asm volatile(
                        "mma.sync.aligned.m16n8k16.row.col.f32.f16.f16.f32 "
                        "{%0,%1,%2,%3}, {%4,%5,%6,%7}, {%8,%9}, {%0,%1,%2,%3};"
                        : "+f"(acc[mt][nt][0]), "+f"(acc[mt][nt][1]),
                          "+f"(acc[mt][nt][2]), "+f"(acc[mt][nt][3])
                        : "r"(a0), "r"(a1), "r"(a2), "r"(a3), "r"(b0), "r"(b1r));
                }
            }
        }
    };

    const int hsel = (warp_n >> 2) * 16384;

    // ================= GEMM1 =================
#pragma unroll
    for (int s = 0; s < NS1; s++) {
        if (s == 0) MBARRIER_WAIT_PARITY(mbarA, 0);
        MBARRIER_WAIT_PARITY(smem_to_u32(&mbars[s & 1]), (s >> 1) & 1);
        const __half* Bslot = smB + (s & 1) * SLOT + hsel;
#pragma unroll
        for (int sub = 0; sub < 4; sub++)
            do_sub(sm, AS, s * 128 + sub * 32, Bslot + sub * 4096);
        __syncthreads();
        if (tid == 0 && s + 2 < NSTG) issueB(s + 2);
    }

    // ---- H epilogue: bias1 + relu -> Hs ----
    {
        const float* br = b1 + r * D;
#pragma unroll
        for (int mt = 0; mt < 2; mt++) {
            int rA = warp_m * 32 + mt * 16 + g;
#pragma unroll
            for (int nt = 0; nt < 4; nt++) {
                int col = warp_n * 32 + nt * 8 + 2 * t4;
                float bx = br[col], by = br[col + 1];
                float x0 = fmaxf(acc[mt][nt][0] + bx, 0.f);
                float y0 = fmaxf(acc[mt][nt][1] + by, 0.f);
                float x1 = fmaxf(acc[mt][nt][2] + bx, 0.f);
                float y1 = fmaxf(acc[mt][nt][3] + by, 0.f);
                int hoff = (col >> 5) * 32 + pos32(col & 31);
                *(__half2*)(Hs + rA * HS + hoff)       = __floats2half2_rn(x0, y0);
                *(__half2*)(Hs + (rA + 8) * HS + hoff) = __floats2half2_rn(x1, y1);
            }
        }
    }
    __syncthreads();

    // ================= GEMM2 (A = Hs) =================
#pragma unroll
    for (int mt = 0; mt < 2; mt++)
#pragma unroll
        for (int nt = 0; nt < 4; nt++)
#pragma unroll
            for (int c = 0; c < 4; c++) acc[mt][nt][c] = 0.f;

#pragma unroll
    for (int s2 = 0; s2 < NS2; s2++) {
        int gs = NS1 + s2;
        MBARRIER_WAIT_PARITY(smem_to_u32(&mbars[gs & 1]), (gs >> 1) & 1);
        const __half* Bslot = smB + (gs & 1) * SLOT + hsel;
#pragma unroll
        for (int sub = 0; sub < 4; sub++)
            do_sub(Hs, HS, s2 * 128 + sub * 32, Bslot + sub * 4096);
    }

    // allow next layer's CTAs to launch (they gridsync before reading our output)
    GRIDDEP_LAUNCH();

    // ---- C epilogue: bias2 -> g_storeh + per-row logit partials (fp32) ----
    float prA[2] = {0.f, 0.f}, prB[2] = {0.f, 0.f};
    {
        __half* Cbase = g_storeh + (size_t)(N0 + layer * NL) * D;
        const float* br = b2 + r * D;
#pragma unroll
        for (int mt = 0; mt < 2; mt++) {
            int mr0 = m0 + warp_m * 32 + mt * 16 + g;
#pragma unroll
            for (int nt = 0; nt < 4; nt++) {
                int col = warp_n * 32 + nt * 8 + 2 * t4;
                float bx = br[col], by = br[col + 1];
                float x0 = acc[mt][nt][0] + bx, y0 = acc[mt][nt][1] + by;
                float x1 = acc[mt][nt][2] + bx, y1 = acc[mt][nt][3] + by;
                int hoff = (col >> 5) * 32 + pos32(col & 31);
                *(__half2*)(Cbase + (size_t)mr0 * D + hoff)       = __floats2half2_rn(x0, y0);
                *(__half2*)(Cbase + (size_t)(mr0 + 8) * D + hoff) = __floats2half2_rn(x1, y1);
                float2 wp = *(const float2*)(eval_w + col);
                prA[mt] += x0 * wp.x + y0 * wp.y;
                prB[mt] += x1 * wp.x + y1 * wp.y;
            }
        }
    }
    // reduce logit partials across t4 lanes (lanes g*4+t4 share the row)
#pragma unroll
    for (int mt = 0; mt < 2; mt++) {
        prA[mt] += __shfl_xor_sync(0xffffffffu, prA[mt], 1);
        prA[mt] += __shfl_xor_sync(0xffffffffu, prA[mt], 2);
        prB[mt] += __shfl_xor_sync(0xffffffffu, prB[mt], 1);
        prB[mt] += __shfl_xor_sync(0xffffffffu, prB[mt], 2);
    }
    __syncthreads();                       // all B-slot reads done -> reuse as scratch
    float* sred = (float*)smB;             // 64 rows x 8 warp_n
    float* sb   = sred + 512;              // 64 rows x 5
    if (t4 == 0) {
#pragma unroll
        for (int mt = 0; mt < 2; mt++) {
            int rA = warp_m * 32 + mt * 16 + g;
            sred[rA * 8 + warp_n]       = prA[mt];
            sred[(rA + 8) * 8 + warp_n] = prB[mt];
        }
    }
    __syncthreads();
    if (tid < 64) {
        float s8 = 0.f;
#pragma unroll
        for (int wn = 0; wn < 8; wn++) s8 += sred[tid * 8 + wn];
        int node = N0 + layer * NL + m0 + tid;
        float o[5];
        bce5(s8 + *eval_b, pos_vals[node], neg_vals[node], *pos_weight, o);
#pragma unroll
        for (int c = 0; c < 5; c++) sb[tid * 5 + c] = o[c];
    }
    __syncthreads();
    if (tid < 5) {
        float t = 0.f;
        for (int i = 0; i < 64; i++) t += sb[i * 5 + tid];
        g_partials[(layer * 128 + bid) * 5 + tid] = t;
    }
}

// ---------------- final reduce: 896 slots x 5, deterministic ----------------
__global__ void final_reduce(float* __restrict__ out, int out_size) {
    const int lane = threadIdx.x;
    float s[5] = {0.f, 0.f, 0.f, 0.f, 0.f};
    for (int i = lane; i < NSLOTS; i += 32)
#pragma unroll
        for (int c = 0; c < 5; c++) s[c] += g_partials[i * 5 + c];
#pragma unroll
    for (int c = 0; c < 5; c++)
#pragma unroll
        for (int off = 16; off; off >>= 1)
            s[c] += __shfl_xor_sync(0xffffffffu, s[c], off);
    if (lane == 0) {
        float pos_rate = (s[3] > 0.f) ? s[1] / fmaxf(s[3], 1e-9f) : 1.f;
        float neg_rate = (s[4] > 0.f) ? s[2] / fmaxf(s[4], 1e-9f) : 1.f;
        if (out_size >= 1) out[0] = s[0];
        if (out_size >= 2) out[1] = pos_rate;
        if (out_size >= 3) out[2] = neg_rate;
    }
}

// ---------------- launch ----------------
extern "C" void kernel_launch(void* const* d_in, const int* in_sizes, int n_in,
                              void* d_out, int out_size) {
    const int*   thax       = (const int*)  d_in[0];
    const int*   par_idx    = (const int*)  d_in[1];
    const float* pos_vals   = (const float*)d_in[2];
    const float* neg_vals   = (const float*)d_in[3];
    const float* init_table = (const float*)d_in[4];
    const float* W1         = (const float*)d_in[5];
    const float* b1         = (const float*)d_in[6];
    const float* W2         = (const float*)d_in[7];
    const float* b2         = (const float*)d_in[8];
    const float* eval_w     = (const float*)d_in[9];
    const float* eval_b     = (const float*)d_in[10];
    const float* pos_weight = (const float*)d_in[11];
    float* out = (float*)d_out;

    cudaFuncSetAttribute(layer_fused,
                         cudaFuncAttributeMaxDynamicSharedMemorySize, SMEM_BYTES);

    prologue<<<128 + 256 + 128, 256>>>(thax, init_table, W1, W2,
                                       pos_vals, neg_vals, eval_w, eval_b, pos_weight);

    for (int l = 0; l < L; l++) {
        cudaLaunchConfig_t cfg = {};
        cfg.gridDim = dim3(NL / 64, 1, 1);
        cfg.blockDim = dim3(512, 1, 1);
        cfg.dynamicSmemBytes = SMEM_BYTES;
        cfg.stream = 0;
        cudaLaunchAttribute attr[1];
        attr[0].id = cudaLaunchAttributeProgrammaticStreamSerialization;
        attr[0].val.programmaticStreamSerializationAllowed = 1;
        cfg.attrs = attr;
        cfg.numAttrs = (l > 0) ? 1 : 0;    // layer 0 must wait for prologue (weights)
        cudaLaunchKernelEx(&cfg, layer_fused,
                           b1, b2, (const int*)(par_idx + (size_t)l * NL * 2), l,
                           pos_vals, neg_vals, eval_w, eval_b, pos_weight);
    }

    final_reduce<<<1, 32>>>(out, out_size);
}